// round 14
// baseline (speedup 1.0000x reference)
#include <cuda_runtime.h>
#include <cuda_fp16.h>
#include <cstdint>

typedef unsigned long long u64;
#define FULLM 0xffffffffu

#define NMAX 50048
__device__ float  g_agg_h[(size_t)NMAX * 64];
__device__ float4 g_sum4[NMAX];
#define PACKE_BYTES 34048   // W1A 8K | W1B 8K | W2 8K | WC 8K | misc 1280
#define PACKN_BYTES 25088   // NW1A 8K | NW1B 8K | NW2 8K | misc 512
__device__ __align__(16) char g_packE[PACKE_BYTES];
__device__ __align__(16) char g_packN[PACKN_BYTES];
__device__ unsigned g_bcnt[2];
__device__ unsigned g_brel[2];

// ===========================================================================
// helpers
// ===========================================================================
__device__ __forceinline__ uint32_t smem_to_u32(const void* p) {
    uint32_t a;
    asm("{ .reg .u64 t; cvta.to.shared.u64 t, %1; cvt.u32.u64 %0, t; }" : "=r"(a) : "l"(p));
    return a;
}
__device__ __forceinline__ void ldsm4(uint32_t r[4], uint32_t addr) {
    asm volatile("ldmatrix.sync.aligned.m8n8.x4.shared.b16 {%0,%1,%2,%3}, [%4];"
        : "=r"(r[0]), "=r"(r[1]), "=r"(r[2]), "=r"(r[3]) : "r"(addr));
}
__device__ __forceinline__ void mma_f16(float c[4], const uint32_t a[4],
                                        uint32_t b0, uint32_t b1) {
    asm volatile("mma.sync.aligned.m16n8k16.row.col.f32.f16.f16.f32 "
        "{%0,%1,%2,%3},{%4,%5,%6,%7},{%8,%9},{%0,%1,%2,%3};"
        : "+f"(c[0]), "+f"(c[1]), "+f"(c[2]), "+f"(c[3])
        : "r"(a[0]), "r"(a[1]), "r"(a[2]), "r"(a[3]), "r"(b0), "r"(b1));
}
__device__ __forceinline__ uint32_t pack2h(float a, float b) {
    __half2 hh = __floats2half2_rn(a, b);
    return *(uint32_t*)&hh;
}
__device__ __forceinline__ void putw16(char* base, int plane, int j, int k, float x) {
    __half hb = __float2half_rn(x);
    uint32_t off = (uint32_t)(j * 128 + ((k * 2) ^ ((j & 7) << 4)));
    *(__half*)(base + plane + off) = hb;
}
__device__ __forceinline__ float4 ldcg4(const void* p) {
    float4 v;
    asm volatile("ld.global.cg.v4.f32 {%0,%1,%2,%3}, [%4];"
        : "=f"(v.x), "=f"(v.y), "=f"(v.z), "=f"(v.w) : "l"(p));
    return v;
}
__device__ __forceinline__ uint4 ldcg4u(const void* p) {
    uint4 v;
    asm volatile("ld.global.cg.v4.u32 {%0,%1,%2,%3}, [%4];"
        : "=r"(v.x), "=r"(v.y), "=r"(v.z), "=r"(v.w) : "l"(p));
    return v;
}

// grid-wide barrier (all 148 blocks resident; replay-safe)
__device__ __forceinline__ void grid_barrier(int i, int tid, int nblk) {
    __threadfence();
    __syncthreads();
    if (tid == 0) {
        unsigned old = atomicAdd(&g_bcnt[i], 1);
        if (old == (unsigned)(nblk - 1)) {
            atomicExch(&g_bcnt[i], 0);
            __threadfence();
            atomicExch(&g_brel[i], 1);
        } else {
            while (atomicAdd(&g_brel[i], 0) == 0) {}
        }
    }
    __syncthreads();
}

// ===========================================================================
// smem layout (edge phase):  weights 0..32768 | A 32768..73728 | misc 73728
// node phase reuses: weights 0..24576 | misc 24576 | A 32768..73728
// ===========================================================================
#define ETPB 320
#define EWARPS 10
#define NBLK 148
#define W1A_HI   0
#define W1B_HI   8192
#define W2_HI    16384
#define WC_HI    24576
#define A_OFF    32768
#define MISC_OFF (A_OFF + EWARPS * 4096)     // 73728
#define SMEM_F   (MISC_OFF + 1280)
#define NW2      16384
#define NMISC    24576

__global__ __launch_bounds__(ETPB, 1) void fused_kernel(
    const float* __restrict__ h, const float* __restrict__ coord,
    const float* __restrict__ vel,
    const int* __restrict__ eidx, int E, int N,
    const float* __restrict__ We1, const float* __restrict__ be1,
    const float* __restrict__ We2, const float* __restrict__ be2,
    const float* __restrict__ Wc1, const float* __restrict__ bc1,
    const float* __restrict__ Wc2, const float* __restrict__ bc2,
    const float* __restrict__ Wn1, const float* __restrict__ bn1,
    const float* __restrict__ Wn2, const float* __restrict__ bn2,
    float* __restrict__ out_h, float* __restrict__ out_coord,
    float* __restrict__ out_v)
{
    extern __shared__ char sm[];
    const uint32_t smb = smem_to_u32(sm);
    const int tid = threadIdx.x;

    // ---- replay-safe: reset release flags before arriving anywhere ----
    if (tid == 0) {
        atomicExch(&g_brel[0], 0);
        atomicExch(&g_brel[1], 0);
    }

    // ================= PHASE 0: zero accumulators + pack weights =================
    {
        int gid = blockIdx.x * ETPB + tid;
        int stride = NBLK * ETPB;
        float4 z = make_float4(0.f, 0.f, 0.f, 0.f);
        for (int i = gid; i < N * 17; i += stride) {
            if (i < N * 16) ((float4*)g_agg_h)[i] = z;
            else            g_sum4[i - N * 16] = z;
        }
        float* miscE = (float*)(g_packE + 32768);
        float* miscN = (float*)(g_packN + 24576);
        if (gid < 129 * 64) {
            int k = gid >> 6, j = gid & 63;
            float x = We1[gid];
            if (k < 128) putw16(g_packE, (k < 64) ? 0 : 8192, j, k & 63, x);
            else         miscE[256 + j] = x;
        }
        if (gid < 64 * 64) {
            int k = gid >> 6, j = gid & 63;
            putw16(g_packE, 16384, j, k, We2[gid]);
            putw16(g_packE, 24576, j, k, Wc1[gid]);
            putw16(g_packN, 16384, j, k, Wn2[gid]);
        }
        if (gid < 128 * 64) {
            int k = gid >> 6, j = gid & 63;
            putw16(g_packN, (k < 64) ? 0 : 8192, j, k & 63, Wn1[gid]);
        }
        if (gid < 64)        { miscE[gid] = be1[gid];          miscN[gid] = bn1[gid]; }
        else if (gid < 128)  { miscE[gid] = be2[gid - 64];     miscN[gid] = bn2[gid - 64]; }
        else if (gid < 192)  { miscE[gid] = bc1[gid - 128]; }
        else if (gid < 256)  { miscE[gid] = Wc2[gid - 192]; }
    }
    grid_barrier(0, tid, NBLK);

    // ================= PHASE 1: edge =================
    float* sMisc = (float*)(sm + MISC_OFF);
    {
        uint4* dst = (uint4*)sm;
        for (int i = tid; i < 2048; i += ETPB) dst[i] = ldcg4u((const uint4*)g_packE + i);
        uint4* md = (uint4*)(sm + MISC_OFF);
        if (tid < 80) md[tid] = ldcg4u((const uint4*)(g_packE + 32768) + tid);
    }
    const float bc2v = bc2[0];
    __syncthreads();

    const int warp = tid >> 5, lane = tid & 31;
    char* aPtr = sm + A_OFF + warp * 4096;
    const uint32_t aHi = smb + A_OFF + warp * 4096;

    const int aRowL = ((lane >> 3) & 1) * 8 + (lane & 7);
    const int aCbL  = ((lane >> 4) & 1) * 16;
    const int bRowL = ((lane >> 4) & 1) * 8 + (lane & 7);
    const int bCbL  = ((lane >> 3) & 1) * 16;
    const int q2 = (lane & 3) * 2;
    const int qr = lane >> 2;

    const int estride = NBLK * ETPB;

    for (int e0 = (blockIdx.x * EWARPS + warp) * 32; e0 < E; e0 += estride) {
        int e = e0 + lane;
        bool valid = e < E;
        int ec = valid ? e : (E - 1);
        int r = eidx[ec], cI = eidx[E + ec];
        float dx = coord[r * 3 + 0] - coord[cI * 3 + 0];
        float dy = coord[r * 3 + 1] - coord[cI * 3 + 1];
        float dz = coord[r * 3 + 2] - coord[cI * 3 + 2];
        float rad = valid ? (dx * dx + dy * dy + dz * dz) : 0.f;
        int rI = valid ? r : -1;

        // C init = be1 + rad * w1rad
        float C[2][8][4];
        #pragma unroll
        for (int m = 0; m < 2; m++) {
            float rad0 = __shfl_sync(FULLM, rad, m * 16 + qr);
            float rad1 = __shfl_sync(FULLM, rad, m * 16 + 8 + qr);
            #pragma unroll
            for (int nt = 0; nt < 8; nt++) {
                int col0 = nt * 8 + q2;
                float2 bb = *(float2*)(sMisc + col0);
                float2 wr = *(float2*)(sMisc + 256 + col0);
                C[m][nt][0] = fmaf(rad0, wr.x, bb.x);
                C[m][nt][1] = fmaf(rad0, wr.y, bb.y);
                C[m][nt][2] = fmaf(rad1, wr.x, bb.x);
                C[m][nt][3] = fmaf(rad1, wr.y, bb.y);
            }
        }

        // GEMM1
        #pragma unroll
        for (int half = 0; half < 2; half++) {
            __syncwarp();
            #pragma unroll
            for (int i = 0; i < 16; i++) {
                int edge = (i << 1) | (lane >> 4);
                int node = __shfl_sync(FULLM, half ? cI : r, edge);
                float4 v = *(const float4*)(h + (size_t)node * 64 + (lane & 15) * 4);
                uint32_t h0 = pack2h(v.x, v.y);
                uint32_t h1 = pack2h(v.z, v.w);
                uint32_t off = (uint32_t)(edge * 128 + (((lane & 15) * 8) ^ ((edge & 7) << 4)));
                *(uint2*)(aPtr + off) = make_uint2(h0, h1);
            }
            __syncwarp();

            const uint32_t wB = smb + (half ? W1B_HI : W1A_HI);
            #pragma unroll
            for (int kt = 0; kt < 4; kt++) {
                uint32_t Ah[2][4];
                #pragma unroll
                for (int m = 0; m < 2; m++) {
                    int ar = m * 16 + aRowL;
                    uint32_t ad = aHi + ar * 128 + ((kt * 32 + aCbL) ^ ((ar & 7) << 4));
                    ldsm4(Ah[m], ad);
                }
                #pragma unroll
                for (int nt2 = 0; nt2 < 4; nt2++) {
                    uint32_t Bh[4];
                    int br = nt2 * 16 + bRowL;
                    uint32_t bd = wB + br * 128 + ((kt * 32 + bCbL) ^ ((br & 7) << 4));
                    ldsm4(Bh, bd);
                    #pragma unroll
                    for (int m = 0; m < 2; m++)
                        #pragma unroll
                        for (int p = 0; p < 2; p++)
                            mma_f16(C[m][nt2 * 2 + p], Ah[m], Bh[2 * p], Bh[2 * p + 1]);
                }
            }
        }

        // epi1: relu -> A2; C2 init = be2
        uint32_t A2h[2][4][4];
        float C2[2][8][4];
        #pragma unroll
        for (int nt = 0; nt < 8; nt++) {
            int col0 = nt * 8 + q2;
            float2 b2 = *(float2*)(sMisc + 64 + col0);
            #pragma unroll
            for (int m = 0; m < 2; m++) {
                float c0 = fmaxf(C[m][nt][0], 0.f);
                float c1 = fmaxf(C[m][nt][1], 0.f);
                float c2 = fmaxf(C[m][nt][2], 0.f);
                float c3 = fmaxf(C[m][nt][3], 0.f);
                int kt = nt >> 1, o = (nt & 1) * 2;
                A2h[m][kt][o]     = pack2h(c0, c1);
                A2h[m][kt][o + 1] = pack2h(c2, c3);
                C2[m][nt][0] = b2.x; C2[m][nt][1] = b2.y;
                C2[m][nt][2] = b2.x; C2[m][nt][3] = b2.y;
            }
        }

        // GEMM2
        #pragma unroll
        for (int kt = 0; kt < 4; kt++) {
            #pragma unroll
            for (int nt2 = 0; nt2 < 4; nt2++) {
                uint32_t Bh[4];
                int br = nt2 * 16 + bRowL;
                uint32_t bd = smb + W2_HI + br * 128 + ((kt * 32 + bCbL) ^ ((br & 7) << 4));
                ldsm4(Bh, bd);
                #pragma unroll
                for (int m = 0; m < 2; m++)
                    #pragma unroll
                    for (int p = 0; p < 2; p++)
                        mma_f16(C2[m][nt2 * 2 + p], A2h[m][kt], Bh[2 * p], Bh[2 * p + 1]);
            }
        }

        // epi2: feat = relu(C2); atomics; A3; C3 init = bc1
        uint32_t A3h[2][4][4];
        float C3[2][8][4];
        #pragma unroll
        for (int m = 0; m < 2; m++) {
            int rr0 = __shfl_sync(FULLM, rI, m * 16 + qr);
            int rr1 = __shfl_sync(FULLM, rI, m * 16 + 8 + qr);
            #pragma unroll
            for (int nt = 0; nt < 8; nt++) {
                int col0 = nt * 8 + q2;
                float2 bc = *(float2*)(sMisc + 128 + col0);
                float f0 = fmaxf(C2[m][nt][0], 0.f);
                float f1 = fmaxf(C2[m][nt][1], 0.f);
                float f2 = fmaxf(C2[m][nt][2], 0.f);
                float f3 = fmaxf(C2[m][nt][3], 0.f);
                int kt = nt >> 1, o = (nt & 1) * 2;
                A3h[m][kt][o]     = pack2h(f0, f1);
                A3h[m][kt][o + 1] = pack2h(f2, f3);
                C3[m][nt][0] = bc.x; C3[m][nt][1] = bc.y;
                C3[m][nt][2] = bc.x; C3[m][nt][3] = bc.y;
                float g0 = __shfl_xor_sync(FULLM, f0, 1);
                float g1 = __shfl_xor_sync(FULLM, f1, 1);
                float g2 = __shfl_xor_sync(FULLM, f2, 1);
                float g3 = __shfl_xor_sync(FULLM, f3, 1);
                if ((lane & 1) == 0) {
                    int cb = nt * 8 + ((lane & 3) >> 1) * 4;
                    if (rr0 >= 0)
                        atomicAdd((float4*)(g_agg_h + (size_t)rr0 * 64 + cb),
                                  make_float4(f0, f1, g0, g1));
                    if (rr1 >= 0)
                        atomicAdd((float4*)(g_agg_h + (size_t)rr1 * 64 + cb),
                                  make_float4(f2, f3, g2, g3));
                }
            }
        }

        // GEMM3 (gate)
        #pragma unroll
        for (int kt = 0; kt < 4; kt++) {
            #pragma unroll
            for (int nt2 = 0; nt2 < 4; nt2++) {
                uint32_t Bh[4];
                int br = nt2 * 16 + bRowL;
                uint32_t bd = smb + WC_HI + br * 128 + ((kt * 32 + bCbL) ^ ((br & 7) << 4));
                ldsm4(Bh, bd);
                #pragma unroll
                for (int m = 0; m < 2; m++)
                    #pragma unroll
                    for (int p = 0; p < 2; p++)
                        mma_f16(C3[m][nt2 * 2 + p], A3h[m][kt], Bh[2 * p], Bh[2 * p + 1]);
            }
        }

        // epi3
        #pragma unroll
        for (int m = 0; m < 2; m++) {
            float p0 = 0.f, p1 = 0.f;
            #pragma unroll
            for (int nt = 0; nt < 8; nt++) {
                int col0 = nt * 8 + q2;
                float2 w2 = *(float2*)(sMisc + 192 + col0);
                p0 += fmaxf(C3[m][nt][0], 0.f) * w2.x + fmaxf(C3[m][nt][1], 0.f) * w2.y;
                p1 += fmaxf(C3[m][nt][2], 0.f) * w2.x + fmaxf(C3[m][nt][3], 0.f) * w2.y;
            }
            p0 += __shfl_xor_sync(FULLM, p0, 1);
            p0 += __shfl_xor_sync(FULLM, p0, 2);
            p1 += __shfl_xor_sync(FULLM, p1, 1);
            p1 += __shfl_xor_sync(FULLM, p1, 2);

            int row0 = m * 16 + qr, row1 = row0 + 8;
            float gx0 = __shfl_sync(FULLM, dx, row0), gy0 = __shfl_sync(FULLM, dy, row0),
                  gz0 = __shfl_sync(FULLM, dz, row0);
            float gx1 = __shfl_sync(FULLM, dx, row1), gy1 = __shfl_sync(FULLM, dy, row1),
                  gz1 = __shfl_sync(FULLM, dz, row1);
            int r0v = __shfl_sync(FULLM, rI, row0);
            int r1v = __shfl_sync(FULLM, rI, row1);

            if ((lane & 3) == 0) {
                if (r0v >= 0) {
                    float gt = p0 + bc2v;
                    atomicAdd(&g_sum4[r0v], make_float4(
                        fminf(fmaxf(gx0 * gt, -100.f), 100.f),
                        fminf(fmaxf(gy0 * gt, -100.f), 100.f),
                        fminf(fmaxf(gz0 * gt, -100.f), 100.f), 1.f));
                }
                if (r1v >= 0) {
                    float gt = p1 + bc2v;
                    atomicAdd(&g_sum4[r1v], make_float4(
                        fminf(fmaxf(gx1 * gt, -100.f), 100.f),
                        fminf(fmaxf(gy1 * gt, -100.f), 100.f),
                        fminf(fmaxf(gz1 * gt, -100.f), 100.f), 1.f));
                }
            }
        }
    }

    grid_barrier(1, tid, NBLK);

    // ================= PHASE 2: coord update + node =================
    for (int i = blockIdx.x * ETPB + tid; i < N; i += NBLK * ETPB) {
        float4 s = ldcg4(&g_sum4[i]);
        float c = s.w;
        float invc = (c > 0.f) ? (1.f / fmaxf(c, 1.f)) : 0.f;
        float vx = vel[i * 3 + 0] + s.x * invc * 0.125f;
        float vy = vel[i * 3 + 1] + s.y * invc * 0.125f;
        float vz = vel[i * 3 + 2] + s.z * invc * 0.125f;
        out_v[i * 3 + 0] = vx;
        out_v[i * 3 + 1] = vy;
        out_v[i * 3 + 2] = vz;
        out_coord[i * 3 + 0] = coord[i * 3 + 0] + vx * 0.125f;
        out_coord[i * 3 + 1] = coord[i * 3 + 1] + vy * 0.125f;
        out_coord[i * 3 + 2] = coord[i * 3 + 2] + vz * 0.125f;
    }

    {
        uint4* dst = (uint4*)sm;
        for (int i = tid; i < 1536; i += ETPB) dst[i] = ldcg4u((const uint4*)g_packN + i);
        uint4* md = (uint4*)(sm + NMISC);
        if (tid < 32) md[tid] = ldcg4u((const uint4*)(g_packN + 24576) + tid);
    }
    __syncthreads();
    float* sMiscN = (float*)(sm + NMISC);

    const int ntiles = (N + 31) >> 5;
    for (int t = blockIdx.x * EWARPS + warp; t < ntiles; t += NBLK * EWARPS) {
        const int nbase = t << 5;

        float C[2][8][4];
        #pragma unroll
        for (int nt = 0; nt < 8; nt++) {
            int col0 = nt * 8 + q2;
            float2 bb = *(float2*)(sMiscN + col0);
            #pragma unroll
            for (int m = 0; m < 2; m++) {
                C[m][nt][0] = bb.x; C[m][nt][1] = bb.y;
                C[m][nt][2] = bb.x; C[m][nt][3] = bb.y;
            }
        }

        #pragma unroll
        for (int half = 0; half < 2; half++) {
            __syncwarp();
            #pragma unroll
            for (int i = 0; i < 16; i++) {
                int row = (i << 1) | (lane >> 4);
                int node = nbase + row;
                if (node >= N) node = N - 1;
                float4 v;
                if (half)
                    v = ldcg4(g_agg_h + (size_t)node * 64 + (lane & 15) * 4);
                else
                    v = *(const float4*)(h + (size_t)node * 64 + (lane & 15) * 4);
                uint32_t h0 = pack2h(v.x, v.y);
                uint32_t h1 = pack2h(v.z, v.w);
                uint32_t off = (uint32_t)(row * 128 + (((lane & 15) * 8) ^ ((row & 7) << 4)));
                *(uint2*)(aPtr + off) = make_uint2(h0, h1);
            }
            __syncwarp();

            const uint32_t wB = smb + (half ? 8192 : 0);
            #pragma unroll
            for (int kt = 0; kt < 4; kt++) {
                uint32_t Ah[2][4];
                #pragma unroll
                for (int m = 0; m < 2; m++) {
                    int ar = m * 16 + aRowL;
                    uint32_t ad = aHi + ar * 128 + ((kt * 32 + aCbL) ^ ((ar & 7) << 4));
                    ldsm4(Ah[m], ad);
                }
                #pragma unroll
                for (int nt2 = 0; nt2 < 4; nt2++) {
                    uint32_t Bh[4];
                    int br = nt2 * 16 + bRowL;
                    uint32_t bd = wB + br * 128 + ((kt * 32 + bCbL) ^ ((br & 7) << 4));
                    ldsm4(Bh, bd);
                    #pragma unroll
                    for (int m = 0; m < 2; m++)
                        #pragma unroll
                        for (int p = 0; p < 2; p++)
                            mma_f16(C[m][nt2 * 2 + p], Ah[m], Bh[2 * p], Bh[2 * p + 1]);
                }
            }
        }

        uint32_t A2h[2][4][4];
        float C2[2][8][4];
        #pragma unroll
        for (int nt = 0; nt < 8; nt++) {
            int col0 = nt * 8 + q2;
            float2 b2 = *(float2*)(sMiscN + 64 + col0);
            #pragma unroll
            for (int m = 0; m < 2; m++) {
                float c0 = fmaxf(C[m][nt][0], 0.f);
                float c1 = fmaxf(C[m][nt][1], 0.f);
                float c2 = fmaxf(C[m][nt][2], 0.f);
                float c3 = fmaxf(C[m][nt][3], 0.f);
                int kt = nt >> 1, o = (nt & 1) * 2;
                A2h[m][kt][o]     = pack2h(c0, c1);
                A2h[m][kt][o + 1] = pack2h(c2, c3);
                C2[m][nt][0] = b2.x; C2[m][nt][1] = b2.y;
                C2[m][nt][2] = b2.x; C2[m][nt][3] = b2.y;
            }
        }

        #pragma unroll
        for (int kt = 0; kt < 4; kt++) {
            #pragma unroll
            for (int nt2 = 0; nt2 < 4; nt2++) {
                uint32_t Bh[4];
                int br = nt2 * 16 + bRowL;
                uint32_t bd = smb + NW2 + br * 128 + ((kt * 32 + bCbL) ^ ((br & 7) << 4));
                ldsm4(Bh, bd);
                #pragma unroll
                for (int m = 0; m < 2; m++)
                    #pragma unroll
                    for (int p = 0; p < 2; p++)
                        mma_f16(C2[m][nt2 * 2 + p], A2h[m][kt], Bh[2 * p], Bh[2 * p + 1]);
            }
        }

        #pragma unroll
        for (int m = 0; m < 2; m++) {
            int row0 = nbase + m * 16 + qr;
            int row1 = row0 + 8;
            bool v0 = row0 < N, v1 = row1 < N;
            #pragma unroll
            for (int nt = 0; nt < 8; nt++) {
                int col0 = nt * 8 + q2;
                if (v0) {
                    float2 rs = *(const float2*)(h + (size_t)row0 * 64 + col0);
                    float2 o = make_float2(C2[m][nt][0] + rs.x, C2[m][nt][1] + rs.y);
                    *(float2*)(out_h + (size_t)row0 * 64 + col0) = o;
                }
                if (v1) {
                    float2 rs = *(const float2*)(h + (size_t)row1 * 64 + col0);
                    float2 o = make_float2(C2[m][nt][2] + rs.x, C2[m][nt][3] + rs.y);
                    *(float2*)(out_h + (size_t)row1 * 64 + col0) = o;
                }
            }
        }
    }
}

// ---------------------------------------------------------------------------
extern "C" void kernel_launch(void* const* d_in, const int* in_sizes, int n_in,
                              void* d_out, int out_size)
{
    const float* h     = (const float*)d_in[0];
    const float* coord = (const float*)d_in[1];
    const float* vel   = (const float*)d_in[2];
    const int*   eidx  = (const int*)d_in[4];
    const float* We1 = (const float*)d_in[5];
    const float* be1 = (const float*)d_in[6];
    const float* We2 = (const float*)d_in[7];
    const float* be2 = (const float*)d_in[8];
    const float* Wn1 = (const float*)d_in[9];
    const float* bn1 = (const float*)d_in[10];
    const float* Wn2 = (const float*)d_in[11];
    const float* bn2 = (const float*)d_in[12];
    const float* Wc1 = (const float*)d_in[13];
    const float* bc1 = (const float*)d_in[14];
    const float* Wc2 = (const float*)d_in[15];
    const float* bc2 = (const float*)d_in[16];

    const int N = in_sizes[0] / 64;
    const int E = in_sizes[4] / 2;

    float* out       = (float*)d_out;
    float* out_h     = out;
    float* out_coord = out + (size_t)N * 64;
    float* out_v     = out_coord + (size_t)N * 3;

    cudaFuncSetAttribute(fused_kernel, cudaFuncAttributeMaxDynamicSharedMemorySize, SMEM_F);

    fused_kernel<<<NBLK, ETPB, SMEM_F>>>(h, coord, vel, eidx, E, N,
                                         We1, be1, We2, be2, Wc1, bc1, Wc2, bc2,
                                         Wn1, bn1, Wn2, bn2,
                                         out_h, out_coord, out_v);
}

// round 15
// speedup vs baseline: 1.2881x; 1.2881x over previous
#include <cuda_runtime.h>
#include <cuda_fp16.h>
#include <cstdint>

typedef unsigned long long u64;
#define FULLM 0xffffffffu

#define NMAX 50048
__device__ float  g_agg_h[(size_t)NMAX * 64];
__device__ float4 g_sum4[NMAX];
#define PACKE_BYTES 34048   // W1A 8K | W1B 8K | W2 8K | WC 8K | misc 1280
#define PACKN_BYTES 25088   // NW1A 8K | NW1B 8K | NW2 8K | misc 512
__device__ __align__(16) char g_packE[PACKE_BYTES];
__device__ __align__(16) char g_packN[PACKN_BYTES];

// ===========================================================================
// helpers
// ===========================================================================
__device__ __forceinline__ uint32_t smem_to_u32(const void* p) {
    uint32_t a;
    asm("{ .reg .u64 t; cvta.to.shared.u64 t, %1; cvt.u32.u64 %0, t; }" : "=r"(a) : "l"(p));
    return a;
}
__device__ __forceinline__ void ldsm4(uint32_t r[4], uint32_t addr) {
    asm volatile("ldmatrix.sync.aligned.m8n8.x4.shared.b16 {%0,%1,%2,%3}, [%4];"
        : "=r"(r[0]), "=r"(r[1]), "=r"(r[2]), "=r"(r[3]) : "r"(addr));
}
__device__ __forceinline__ void mma_f16(float c[4], const uint32_t a[4],
                                        uint32_t b0, uint32_t b1) {
    asm volatile("mma.sync.aligned.m16n8k16.row.col.f32.f16.f16.f32 "
        "{%0,%1,%2,%3},{%4,%5,%6,%7},{%8,%9},{%0,%1,%2,%3};"
        : "+f"(c[0]), "+f"(c[1]), "+f"(c[2]), "+f"(c[3])
        : "r"(a[0]), "r"(a[1]), "r"(a[2]), "r"(a[3]), "r"(b0), "r"(b1));
}
__device__ __forceinline__ uint32_t pack2h(float a, float b) {
    __half2 hh = __floats2half2_rn(a, b);
    return *(uint32_t*)&hh;
}
__device__ __forceinline__ void putw16(char* base, int plane, int j, int k, float x) {
    __half hb = __float2half_rn(x);
    uint32_t off = (uint32_t)(j * 128 + ((k * 2) ^ ((j & 7) << 4)));
    *(__half*)(base + plane + off) = hb;
}

// ===========================================================================
// Prep kernel: zero accumulators + pack fp16 weight images
// ===========================================================================
__global__ void prep_kernel(int n,
    const float* __restrict__ We1, const float* __restrict__ be1,
    const float* __restrict__ We2, const float* __restrict__ be2,
    const float* __restrict__ Wc1, const float* __restrict__ bc1,
    const float* __restrict__ Wc2,
    const float* __restrict__ Wn1, const float* __restrict__ bn1,
    const float* __restrict__ Wn2, const float* __restrict__ bn2)
{
    int gid = blockIdx.x * blockDim.x + threadIdx.x;
    int stride = gridDim.x * blockDim.x;
    float4 z = make_float4(0.f, 0.f, 0.f, 0.f);
    for (int i = gid; i < n * 17; i += stride) {
        if (i < n * 16) ((float4*)g_agg_h)[i] = z;
        else            g_sum4[i - n * 16] = z;
    }
    float* miscE = (float*)(g_packE + 32768);
    float* miscN = (float*)(g_packN + 24576);
    if (gid < 129 * 64) {
        int k = gid >> 6, j = gid & 63;
        float x = We1[gid];
        if (k < 128) putw16(g_packE, (k < 64) ? 0 : 8192, j, k & 63, x);
        else         miscE[256 + j] = x;
    }
    if (gid < 64 * 64) {
        int k = gid >> 6, j = gid & 63;
        putw16(g_packE, 16384, j, k, We2[gid]);
        putw16(g_packE, 24576, j, k, Wc1[gid]);
        putw16(g_packN, 16384, j, k, Wn2[gid]);
    }
    if (gid < 128 * 64) {
        int k = gid >> 6, j = gid & 63;
        putw16(g_packN, (k < 64) ? 0 : 8192, j, k & 63, Wn1[gid]);
    }
    if (gid < 64)        { miscE[gid] = be1[gid];            miscN[gid] = bn1[gid]; }
    else if (gid < 128)  { miscE[gid] = be2[gid - 64];       miscN[gid] = bn2[gid - 64]; }
    else if (gid < 192)  { miscE[gid] = bc1[gid - 128]; }
    else if (gid < 256)  { miscE[gid] = Wc2[gid - 192]; }
}

// ===========================================================================
// Edge kernel: pure fp16 HMMA, 384 thr / 12 warps, bias folded into C-init
// ===========================================================================
#define ETPB 384
#define EWARPS 12
#define W1A_HI   0
#define W1B_HI   8192
#define W2_HI    16384
#define WC_HI    24576
#define A_OFF    32768                       // per warp 4096
#define MISC_OFF (A_OFF + EWARPS * 4096)     // 81920
#define SMEM_E   (MISC_OFF + 1280)

__global__ __launch_bounds__(ETPB, 1) void edge_mma_kernel(
    const float* __restrict__ h, const float* __restrict__ coord,
    const int* __restrict__ eidx, int E, const float* __restrict__ bc2)
{
    extern __shared__ char sm[];
    const uint32_t smb = smem_to_u32(sm);
    const int tid = threadIdx.x;
    float* sMisc = (float*)(sm + MISC_OFF);

    {
        const uint4* src = (const uint4*)g_packE;
        uint4* dst = (uint4*)sm;
        for (int i = tid; i < 2048; i += ETPB) dst[i] = src[i];
        const uint4* ms = (const uint4*)(g_packE + 32768);
        uint4* md = (uint4*)(sm + MISC_OFF);
        if (tid < 80) md[tid] = ms[tid];
    }
    const float bc2v = bc2[0];
    __syncthreads();

    const int warp = tid >> 5, lane = tid & 31;
    char* aPtr = sm + A_OFF + warp * 4096;
    const uint32_t aHi = smb + A_OFF + warp * 4096;

    const int aRowL = ((lane >> 3) & 1) * 8 + (lane & 7);
    const int aCbL  = ((lane >> 4) & 1) * 16;
    const int bRowL = ((lane >> 4) & 1) * 8 + (lane & 7);
    const int bCbL  = ((lane >> 3) & 1) * 16;
    const int q2 = (lane & 3) * 2;
    const int qr = lane >> 2;

    const int estride = gridDim.x * ETPB;

    for (int e0 = (blockIdx.x * EWARPS + warp) * 32; e0 < E; e0 += estride) {
        int e = e0 + lane;
        bool valid = e < E;
        int ec = valid ? e : (E - 1);
        int r = eidx[ec], cI = eidx[E + ec];
        float dx = coord[r * 3 + 0] - coord[cI * 3 + 0];
        float dy = coord[r * 3 + 1] - coord[cI * 3 + 1];
        float dz = coord[r * 3 + 2] - coord[cI * 3 + 2];
        float rad = valid ? (dx * dx + dy * dy + dz * dz) : 0.f;
        int rI = valid ? r : -1;

        // ---- C init = be1 + rad * w1rad ----
        float C[2][8][4];
        #pragma unroll
        for (int m = 0; m < 2; m++) {
            float rad0 = __shfl_sync(FULLM, rad, m * 16 + qr);
            float rad1 = __shfl_sync(FULLM, rad, m * 16 + 8 + qr);
            #pragma unroll
            for (int nt = 0; nt < 8; nt++) {
                int col0 = nt * 8 + q2;
                float2 bb = *(float2*)(sMisc + col0);
                float2 wr = *(float2*)(sMisc + 256 + col0);
                C[m][nt][0] = fmaf(rad0, wr.x, bb.x);
                C[m][nt][1] = fmaf(rad0, wr.y, bb.y);
                C[m][nt][2] = fmaf(rad1, wr.x, bb.x);
                C[m][nt][3] = fmaf(rad1, wr.y, bb.y);
            }
        }

        // ================= GEMM1 =================
        #pragma unroll
        for (int half = 0; half < 2; half++) {
            __syncwarp();
            #pragma unroll
            for (int i = 0; i < 16; i++) {
                int edge = (i << 1) | (lane >> 4);
                int node = __shfl_sync(FULLM, half ? cI : r, edge);
                float4 v = *(const float4*)(h + (size_t)node * 64 + (lane & 15) * 4);
                uint32_t h0 = pack2h(v.x, v.y);
                uint32_t h1 = pack2h(v.z, v.w);
                uint32_t off = (uint32_t)(edge * 128 + (((lane & 15) * 8) ^ ((edge & 7) << 4)));
                *(uint2*)(aPtr + off) = make_uint2(h0, h1);
            }
            __syncwarp();

            const uint32_t wB = smb + (half ? W1B_HI : W1A_HI);
            #pragma unroll
            for (int kt = 0; kt < 4; kt++) {
                uint32_t Ah[2][4];
                #pragma unroll
                for (int m = 0; m < 2; m++) {
                    int ar = m * 16 + aRowL;
                    uint32_t ad = aHi + ar * 128 + ((kt * 32 + aCbL) ^ ((ar & 7) << 4));
                    ldsm4(Ah[m], ad);
                }
                #pragma unroll
                for (int nt2 = 0; nt2 < 4; nt2++) {
                    uint32_t Bh[4];
                    int br = nt2 * 16 + bRowL;
                    uint32_t bd = wB + br * 128 + ((kt * 32 + bCbL) ^ ((br & 7) << 4));
                    ldsm4(Bh, bd);
                    #pragma unroll
                    for (int m = 0; m < 2; m++)
                        #pragma unroll
                        for (int p = 0; p < 2; p++)
                            mma_f16(C[m][nt2 * 2 + p], Ah[m], Bh[2 * p], Bh[2 * p + 1]);
                }
            }
        }

        // ---- epi1: relu -> A2 frags; C2 init = be2 ----
        uint32_t A2h[2][4][4];
        float C2[2][8][4];
        #pragma unroll
        for (int nt = 0; nt < 8; nt++) {
            int col0 = nt * 8 + q2;
            float2 b2 = *(float2*)(sMisc + 64 + col0);
            #pragma unroll
            for (int m = 0; m < 2; m++) {
                float c0 = fmaxf(C[m][nt][0], 0.f);
                float c1 = fmaxf(C[m][nt][1], 0.f);
                float c2 = fmaxf(C[m][nt][2], 0.f);
                float c3 = fmaxf(C[m][nt][3], 0.f);
                int kt = nt >> 1, o = (nt & 1) * 2;
                A2h[m][kt][o]     = pack2h(c0, c1);
                A2h[m][kt][o + 1] = pack2h(c2, c3);
                C2[m][nt][0] = b2.x; C2[m][nt][1] = b2.y;
                C2[m][nt][2] = b2.x; C2[m][nt][3] = b2.y;
            }
        }

        // ================= GEMM2 =================
        #pragma unroll
        for (int kt = 0; kt < 4; kt++) {
            #pragma unroll
            for (int nt2 = 0; nt2 < 4; nt2++) {
                uint32_t Bh[4];
                int br = nt2 * 16 + bRowL;
                uint32_t bd = smb + W2_HI + br * 128 + ((kt * 32 + bCbL) ^ ((br & 7) << 4));
                ldsm4(Bh, bd);
                #pragma unroll
                for (int m = 0; m < 2; m++)
                    #pragma unroll
                    for (int p = 0; p < 2; p++)
                        mma_f16(C2[m][nt2 * 2 + p], A2h[m][kt], Bh[2 * p], Bh[2 * p + 1]);
            }
        }

        // ---- epi2: feat = relu(C2); atomics; A3 frags; C3 init = bc1 ----
        uint32_t A3h[2][4][4];
        float C3[2][8][4];
        #pragma unroll
        for (int m = 0; m < 2; m++) {
            int rr0 = __shfl_sync(FULLM, rI, m * 16 + qr);
            int rr1 = __shfl_sync(FULLM, rI, m * 16 + 8 + qr);
            #pragma unroll
            for (int nt = 0; nt < 8; nt++) {
                int col0 = nt * 8 + q2;
                float2 bc = *(float2*)(sMisc + 128 + col0);
                float f0 = fmaxf(C2[m][nt][0], 0.f);
                float f1 = fmaxf(C2[m][nt][1], 0.f);
                float f2 = fmaxf(C2[m][nt][2], 0.f);
                float f3 = fmaxf(C2[m][nt][3], 0.f);
                int kt = nt >> 1, o = (nt & 1) * 2;
                A3h[m][kt][o]     = pack2h(f0, f1);
                A3h[m][kt][o + 1] = pack2h(f2, f3);
                C3[m][nt][0] = bc.x; C3[m][nt][1] = bc.y;
                C3[m][nt][2] = bc.x; C3[m][nt][3] = bc.y;
                float g0 = __shfl_xor_sync(FULLM, f0, 1);
                float g1 = __shfl_xor_sync(FULLM, f1, 1);
                float g2 = __shfl_xor_sync(FULLM, f2, 1);
                float g3 = __shfl_xor_sync(FULLM, f3, 1);
                if ((lane & 1) == 0) {
                    int cb = nt * 8 + ((lane & 3) >> 1) * 4;
                    if (rr0 >= 0)
                        atomicAdd((float4*)(g_agg_h + (size_t)rr0 * 64 + cb),
                                  make_float4(f0, f1, g0, g1));
                    if (rr1 >= 0)
                        atomicAdd((float4*)(g_agg_h + (size_t)rr1 * 64 + cb),
                                  make_float4(f2, f3, g2, g3));
                }
            }
        }

        // ================= GEMM3 (gate) =================
        #pragma unroll
        for (int kt = 0; kt < 4; kt++) {
            #pragma unroll
            for (int nt2 = 0; nt2 < 4; nt2++) {
                uint32_t Bh[4];
                int br = nt2 * 16 + bRowL;
                uint32_t bd = smb + WC_HI + br * 128 + ((kt * 32 + bCbL) ^ ((br & 7) << 4));
                ldsm4(Bh, bd);
                #pragma unroll
                for (int m = 0; m < 2; m++)
                    #pragma unroll
                    for (int p = 0; p < 2; p++)
                        mma_f16(C3[m][nt2 * 2 + p], A3h[m][kt], Bh[2 * p], Bh[2 * p + 1]);
            }
        }

        // ---- epi3 ----
        #pragma unroll
        for (int m = 0; m < 2; m++) {
            float p0 = 0.f, p1 = 0.f;
            #pragma unroll
            for (int nt = 0; nt < 8; nt++) {
                int col0 = nt * 8 + q2;
                float2 w2 = *(float2*)(sMisc + 192 + col0);
                p0 += fmaxf(C3[m][nt][0], 0.f) * w2.x + fmaxf(C3[m][nt][1], 0.f) * w2.y;
                p1 += fmaxf(C3[m][nt][2], 0.f) * w2.x + fmaxf(C3[m][nt][3], 0.f) * w2.y;
            }
            p0 += __shfl_xor_sync(FULLM, p0, 1);
            p0 += __shfl_xor_sync(FULLM, p0, 2);
            p1 += __shfl_xor_sync(FULLM, p1, 1);
            p1 += __shfl_xor_sync(FULLM, p1, 2);

            int row0 = m * 16 + qr, row1 = row0 + 8;
            float gx0 = __shfl_sync(FULLM, dx, row0), gy0 = __shfl_sync(FULLM, dy, row0),
                  gz0 = __shfl_sync(FULLM, dz, row0);
            float gx1 = __shfl_sync(FULLM, dx, row1), gy1 = __shfl_sync(FULLM, dy, row1),
                  gz1 = __shfl_sync(FULLM, dz, row1);
            int r0v = __shfl_sync(FULLM, rI, row0);
            int r1v = __shfl_sync(FULLM, rI, row1);

            if ((lane & 3) == 0) {
                if (r0v >= 0) {
                    float gt = p0 + bc2v;
                    atomicAdd(&g_sum4[r0v], make_float4(
                        fminf(fmaxf(gx0 * gt, -100.f), 100.f),
                        fminf(fmaxf(gy0 * gt, -100.f), 100.f),
                        fminf(fmaxf(gz0 * gt, -100.f), 100.f), 1.f));
                }
                if (r1v >= 0) {
                    float gt = p1 + bc2v;
                    atomicAdd(&g_sum4[r1v], make_float4(
                        fminf(fmaxf(gx1 * gt, -100.f), 100.f),
                        fminf(fmaxf(gy1 * gt, -100.f), 100.f),
                        fminf(fmaxf(gz1 * gt, -100.f), 100.f), 1.f));
                }
            }
        }
    }
}

// ===========================================================================
// Node kernel: pure fp16 HMMA, 256 thr / 8 warps, grid 196 (1 tile/warp)
// ===========================================================================
#define NW2  16384
#define NMISC 24576
#define NA_OFF 25088
#define SMEM_N (NA_OFF + 8 * 4096)

__global__ __launch_bounds__(256, 1) void node_mma_kernel(
    const float* __restrict__ h,
    const float* __restrict__ coord, const float* __restrict__ vel,
    float* __restrict__ out_h, float* __restrict__ out_coord,
    float* __restrict__ out_v, int N)
{
    extern __shared__ char sm[];
    const uint32_t smb = smem_to_u32(sm);
    const int tid = threadIdx.x;
    float* sMisc = (float*)(sm + NMISC);

    for (int i = blockIdx.x * 256 + tid; i < N; i += gridDim.x * 256) {
        float4 s = g_sum4[i];
        float c = s.w;
        float invc = (c > 0.f) ? (1.f / fmaxf(c, 1.f)) : 0.f;
        float vx = vel[i * 3 + 0] + s.x * invc * 0.125f;
        float vy = vel[i * 3 + 1] + s.y * invc * 0.125f;
        float vz = vel[i * 3 + 2] + s.z * invc * 0.125f;
        out_v[i * 3 + 0] = vx;
        out_v[i * 3 + 1] = vy;
        out_v[i * 3 + 2] = vz;
        out_coord[i * 3 + 0] = coord[i * 3 + 0] + vx * 0.125f;
        out_coord[i * 3 + 1] = coord[i * 3 + 1] + vy * 0.125f;
        out_coord[i * 3 + 2] = coord[i * 3 + 2] + vz * 0.125f;
    }

    {
        const uint4* src = (const uint4*)g_packN;
        uint4* dst = (uint4*)sm;
        for (int i = tid; i < 1536; i += 256) dst[i] = src[i];
        const uint4* ms = (const uint4*)(g_packN + 24576);
        uint4* md = (uint4*)(sm + NMISC);
        if (tid < 32) md[tid] = ms[tid];
    }
    __syncthreads();

    const int warp = tid >> 5, lane = tid & 31;
    char* aPtr = sm + NA_OFF + warp * 4096;
    const uint32_t aHi = smb + NA_OFF + warp * 4096;

    const int aRowL = ((lane >> 3) & 1) * 8 + (lane & 7);
    const int aCbL  = ((lane >> 4) & 1) * 16;
    const int bRowL = ((lane >> 4) & 1) * 8 + (lane & 7);
    const int bCbL  = ((lane >> 3) & 1) * 16;
    const int q2 = (lane & 3) * 2;
    const int qr = lane >> 2;

    const int ntiles = (N + 31) >> 5;

    for (int t = blockIdx.x * 8 + warp; t < ntiles; t += gridDim.x * 8) {
        const int nbase = t << 5;

        float C[2][8][4];
        #pragma unroll
        for (int nt = 0; nt < 8; nt++) {
            int col0 = nt * 8 + q2;
            float2 bb = *(float2*)(sMisc + col0);
            #pragma unroll
            for (int m = 0; m < 2; m++) {
                C[m][nt][0] = bb.x; C[m][nt][1] = bb.y;
                C[m][nt][2] = bb.x; C[m][nt][3] = bb.y;
            }
        }

        #pragma unroll
        for (int half = 0; half < 2; half++) {
            __syncwarp();
            const float* src = half ? g_agg_h : h;
            #pragma unroll
            for (int i = 0; i < 16; i++) {
                int row = (i << 1) | (lane >> 4);
                int node = nbase + row;
                if (node >= N) node = N - 1;
                float4 v = *(const float4*)(src + (size_t)node * 64 + (lane & 15) * 4);
                uint32_t h0 = pack2h(v.x, v.y);
                uint32_t h1 = pack2h(v.z, v.w);
                uint32_t off = (uint32_t)(row * 128 + (((lane & 15) * 8) ^ ((row & 7) << 4)));
                *(uint2*)(aPtr + off) = make_uint2(h0, h1);
            }
            __syncwarp();

            const uint32_t wB = smb + (half ? 8192 : 0);
            #pragma unroll
            for (int kt = 0; kt < 4; kt++) {
                uint32_t Ah[2][4];
                #pragma unroll
                for (int m = 0; m < 2; m++) {
                    int ar = m * 16 + aRowL;
                    uint32_t ad = aHi + ar * 128 + ((kt * 32 + aCbL) ^ ((ar & 7) << 4));
                    ldsm4(Ah[m], ad);
                }
                #pragma unroll
                for (int nt2 = 0; nt2 < 4; nt2++) {
                    uint32_t Bh[4];
                    int br = nt2 * 16 + bRowL;
                    uint32_t bd = wB + br * 128 + ((kt * 32 + bCbL) ^ ((br & 7) << 4));
                    ldsm4(Bh, bd);
                    #pragma unroll
                    for (int m = 0; m < 2; m++)
                        #pragma unroll
                        for (int p = 0; p < 2; p++)
                            mma_f16(C[m][nt2 * 2 + p], Ah[m], Bh[2 * p], Bh[2 * p + 1]);
                }
            }
        }

        uint32_t A2h[2][4][4];
        float C2[2][8][4];
        #pragma unroll
        for (int nt = 0; nt < 8; nt++) {
            int col0 = nt * 8 + q2;
            float2 b2 = *(float2*)(sMisc + 64 + col0);
            #pragma unroll
            for (int m = 0; m < 2; m++) {
                float c0 = fmaxf(C[m][nt][0], 0.f);
                float c1 = fmaxf(C[m][nt][1], 0.f);
                float c2 = fmaxf(C[m][nt][2], 0.f);
                float c3 = fmaxf(C[m][nt][3], 0.f);
                int kt = nt >> 1, o = (nt & 1) * 2;
                A2h[m][kt][o]     = pack2h(c0, c1);
                A2h[m][kt][o + 1] = pack2h(c2, c3);
                C2[m][nt][0] = b2.x; C2[m][nt][1] = b2.y;
                C2[m][nt][2] = b2.x; C2[m][nt][3] = b2.y;
            }
        }

        #pragma unroll
        for (int kt = 0; kt < 4; kt++) {
            #pragma unroll
            for (int nt2 = 0; nt2 < 4; nt2++) {
                uint32_t Bh[4];
                int br = nt2 * 16 + bRowL;
                uint32_t bd = smb + NW2 + br * 128 + ((kt * 32 + bCbL) ^ ((br & 7) << 4));
                ldsm4(Bh, bd);
                #pragma unroll
                for (int m = 0; m < 2; m++)
                    #pragma unroll
                    for (int p = 0; p < 2; p++)
                        mma_f16(C2[m][nt2 * 2 + p], A2h[m][kt], Bh[2 * p], Bh[2 * p + 1]);
            }
        }

        #pragma unroll
        for (int m = 0; m < 2; m++) {
            int row0 = nbase + m * 16 + qr;
            int row1 = row0 + 8;
            bool v0 = row0 < N, v1 = row1 < N;
            #pragma unroll
            for (int nt = 0; nt < 8; nt++) {
                int col0 = nt * 8 + q2;
                if (v0) {
                    float2 rs = *(const float2*)(h + (size_t)row0 * 64 + col0);
                    float2 o = make_float2(C2[m][nt][0] + rs.x, C2[m][nt][1] + rs.y);
                    *(float2*)(out_h + (size_t)row0 * 64 + col0) = o;
                }
                if (v1) {
                    float2 rs = *(const float2*)(h + (size_t)row1 * 64 + col0);
                    float2 o = make_float2(C2[m][nt][2] + rs.x, C2[m][nt][3] + rs.y);
                    *(float2*)(out_h + (size_t)row1 * 64 + col0) = o;
                }
            }
        }
    }
}

// ---------------------------------------------------------------------------
extern "C" void kernel_launch(void* const* d_in, const int* in_sizes, int n_in,
                              void* d_out, int out_size)
{
    const float* h     = (const float*)d_in[0];
    const float* coord = (const float*)d_in[1];
    const float* vel   = (const float*)d_in[2];
    const int*   eidx  = (const int*)d_in[4];
    const float* We1 = (const float*)d_in[5];
    const float* be1 = (const float*)d_in[6];
    const float* We2 = (const float*)d_in[7];
    const float* be2 = (const float*)d_in[8];
    const float* Wn1 = (const float*)d_in[9];
    const float* bn1 = (const float*)d_in[10];
    const float* Wn2 = (const float*)d_in[11];
    const float* bn2 = (const float*)d_in[12];
    const float* Wc1 = (const float*)d_in[13];
    const float* bc1 = (const float*)d_in[14];
    const float* Wc2 = (const float*)d_in[15];
    const float* bc2 = (const float*)d_in[16];

    const int N = in_sizes[0] / 64;
    const int E = in_sizes[4] / 2;

    float* out       = (float*)d_out;
    float* out_h     = out;
    float* out_coord = out + (size_t)N * 64;
    float* out_v     = out_coord + (size_t)N * 3;

    cudaFuncSetAttribute(edge_mma_kernel, cudaFuncAttributeMaxDynamicSharedMemorySize, SMEM_E);
    cudaFuncSetAttribute(node_mma_kernel, cudaFuncAttributeMaxDynamicSharedMemorySize, SMEM_N);

    prep_kernel<<<512, 256>>>(N, We1, be1, We2, be2, Wc1, bc1, Wc2,
                              Wn1, bn1, Wn2, bn2);
    edge_mma_kernel<<<148, ETPB, SMEM_E>>>(h, coord, eidx, E, bc2);
    node_mma_kernel<<<196, 256, SMEM_N>>>(h, coord, vel,
                                          out_h, out_coord, out_v, N);
}